// round 2
// baseline (speedup 1.0000x reference)
#include <cuda_runtime.h>
#include <math.h>

#define NE   16      // electrons
#define NN   4       // nuclei
#define DIM  128     // D
#define KD   64      // K
#define FD   32      // F
#define HD   45      // H
#define HP   48      // H padded
#define ES   112     // same-spin edges
#define EA   128     // anti-spin edges
#define ENE  64      // nuc-elec edges
#define ET   304     // total edges
#define FSTR 33      // feats row stride (bank-conflict pad)
#define HSTR 49      // hidden row stride (bank-conflict pad)

// ---- shared memory layout (floats) ----
#define OFF_FEATS 0
#define SZ_FEATS  (ET * FSTR)          // 10032
#define OFF_ELEC  (OFF_FEATS + SZ_FEATS)
#define SZ_ELEC   (NE * DIM)           // 2048
#define OFF_UPD   (OFF_ELEC + SZ_ELEC)
#define SZ_UPD    (NE * DIM)           // 2048
#define OFF_HX    (OFF_UPD + SZ_UPD)
#define SZ_HX     (2 * NE * KD)        // 2048
#define OFF_WE    (OFF_HX + SZ_HX)
#define SZ_WE     (EA * KD)            // 8192
#define OFF_HID   (OFF_WE + SZ_WE)
#define SZ_HID    (EA * HSTR)          // 6272
#define OFF_W1    (OFF_HID + SZ_HID)
#define SZ_W1     (FD * HP)            // 1536
#define OFF_B1    (OFF_W1 + SZ_W1)
#define SZ_B1     (HP)                 // 48
#define OFF_W2    (OFF_B1 + SZ_B1)
#define SZ_W2     (HP * KD)            // 3072
#define OFF_WBIG  (OFF_W2 + SZ_W2)
#define SZ_WBIG   (KD * DIM)           // 8192 (hW is 128x64 = same size)
#define OFF_Z     (OFF_WBIG + SZ_WBIG)
#define SZ_Z      (NE * KD)            // 1024
#define OFF_YW    (OFF_Z + SZ_Z)
#define SZ_YW     (NN * KD)            // 256
#define SMEM_FLOATS (OFF_YW + SZ_YW)   // 44,776 floats = 179,104 B

__device__ __forceinline__ float silu_f(float x) {
    return x / (1.0f + __expf(-x));
}

__global__ void __launch_bounds__(256, 1)
schnet_kernel(const float* __restrict__ rs,    const float* __restrict__ coords,
              const float* __restrict__ X_tab, const float* __restrict__ Y_w,
              const float* __restrict__ wW1,   const float* __restrict__ wb1,
              const float* __restrict__ wW2,   const float* __restrict__ h0t,
              const float* __restrict__ hW,    const float* __restrict__ gW,
              const int* __restrict__ same_s,  const int* __restrict__ same_r,
              const int* __restrict__ anti_s,  const int* __restrict__ anti_r,
              const int* __restrict__ ne_s,    const int* __restrict__ ne_r,
              float* __restrict__ out)
{
    extern __shared__ float sm[];
    const int b   = blockIdx.x;
    const int tid = threadIdx.x;

    float* feats = sm + OFF_FEATS;
    float* elec  = sm + OFF_ELEC;
    float* upd   = sm + OFF_UPD;
    float* hx    = sm + OFF_HX;
    float* we_s  = sm + OFF_WE;
    float* hid   = sm + OFF_HID;
    float* w1s   = sm + OFF_W1;
    float* b1s   = sm + OFF_B1;
    float* w2s   = sm + OFF_W2;
    float* wbig  = sm + OFF_WBIG;
    float* z_s   = sm + OFF_Z;
    float* yw_s  = sm + OFF_YW;

    // ---- init: elec = X_tab[0,:] broadcast; Y_w to smem ----
    for (int i = tid; i < NE * DIM; i += 256) elec[i] = X_tab[i & (DIM - 1)];
    for (int i = tid; i < NN * KD;  i += 256) yw_s[i] = Y_w[i];

    // ---- feats: once per sample, reused by all 3 layers ----
    const float* rsb = rs + (size_t)b * NE * 3;
    for (int e = tid; e < ET; e += 256) {
        float sx, sy, sz2;
        int r;
        if (e < ES) {
            int s = same_s[e]; r = same_r[e];
            sx = rsb[s*3]; sy = rsb[s*3+1]; sz2 = rsb[s*3+2];
        } else if (e < ES + EA) {
            int q = e - ES; int s = anti_s[q]; r = anti_r[q];
            sx = rsb[s*3]; sy = rsb[s*3+1]; sz2 = rsb[s*3+2];
        } else {
            int q = e - ES - EA; int n = ne_s[q]; r = ne_r[q];
            sx = coords[n*3]; sy = coords[n*3+1]; sz2 = coords[n*3+2];
        }
        float dx = sx - rsb[r*3], dy = sy - rsb[r*3+1], dz = sz2 - rsb[r*3+2];
        float d   = sqrtf(dx*dx + dy*dy + dz*dz);
        float env = d * d * __expf(-d);
        #pragma unroll
        for (int i = 0; i < FD; i++) {
            float q  = (float)i * (1.0f / 31.0f);
            float mu = 10.0f * q * q;
            float sg = (1.0f + 10.0f * q) * (1.0f / 7.0f);
            float t  = (d - mu) / sg;
            feats[e * FSTR + i] = env * __expf(-t * t);
        }
    }
    __syncthreads();

    for (int l = 0; l < 3; l++) {
        // ---- hx (uses elec BEFORE this layer's update) ----
        if (l == 0) {
            // spin_idxs all zero -> hx is the h0_tab[j,0,:] row for every sender
            for (int i = tid; i < 2 * NE * KD; i += 256) {
                int j = i >> 10;
                int k = i & (KD - 1);
                hx[i] = h0t[j * KD + k];
            }
        } else {
            for (int j = 0; j < 2; j++) {
                const float* src = hW + (size_t)((l - 1) * 2 + j) * DIM * KD;
                for (int i = tid; i < DIM * KD; i += 256) wbig[i] = src[i];
                __syncthreads();
                int s  = tid >> 4;
                int k0 = (tid & 15) << 2;
                float4 acc = make_float4(0.f, 0.f, 0.f, 0.f);
                #pragma unroll 8
                for (int d = 0; d < DIM; d++) {
                    float ev = elec[s * DIM + d];
                    float4 w = *(const float4*)&wbig[d * KD + k0];
                    acc.x += ev * w.x; acc.y += ev * w.y;
                    acc.z += ev * w.z; acc.w += ev * w.w;
                }
                *(float4*)&hx[j * NE * KD + s * KD + k0] = acc;
                __syncthreads();
            }
        }
        for (int i = tid; i < NE * DIM; i += 256) upd[i] = 0.f;
        __syncthreads();

        for (int j = 0; j < 3; j++) {
            const int Ej   = (j == 0) ? ES : (j == 1) ? EA : ENE;
            const int foff = (j == 0) ? 0  : (j == 1) ? ES : (ES + EA);

            // ---- stage weights for this (l, j) ----
            const float* W1 = wW1 + (size_t)(l * 3 + j) * FD * HD;
            for (int i = tid; i < FD * HP; i += 256) {
                int f = i / HP, h = i - f * HP;
                w1s[i] = (h < HD) ? W1[f * HD + h] : 0.f;
            }
            if (tid < HP) {
                const float* B1 = wb1 + (size_t)(l * 3 + j) * HD;
                b1s[tid] = (tid < HD) ? B1[tid] : 0.f;
            }
            const float* W2 = wW2 + (size_t)(l * 3 + j) * HD * KD;
            for (int i = tid; i < HP * KD; i += 256) {
                int h = i >> 6;
                w2s[i] = (h < HD) ? W2[i] : 0.f;   // same h*64+k layout
            }
            const float* G = gW + (size_t)(l * 3 + j) * KD * DIM;
            for (int i = tid; i < KD * DIM; i += 256) wbig[i] = G[i];
            __syncthreads();

            // ---- edge MLP hidden: silu(feats @ W1 + b), tiles 4 rows x 3 cols ----
            {
                int ntile = (Ej >> 2) * 16;
                for (int t = tid; t < ntile; t += 256) {
                    int rg = t >> 4, cg = t & 15;
                    int r0 = rg << 2, hc = cg * 3;
                    float a[4][3];
                    #pragma unroll
                    for (int i2 = 0; i2 < 4; i2++)
                        { a[i2][0] = 0.f; a[i2][1] = 0.f; a[i2][2] = 0.f; }
                    const float* fp = &feats[(foff + r0) * FSTR];
                    #pragma unroll
                    for (int f = 0; f < FD; f++) {
                        float w0 = w1s[f * HP + hc];
                        float w1 = w1s[f * HP + hc + 1];
                        float w2 = w1s[f * HP + hc + 2];
                        #pragma unroll
                        for (int i2 = 0; i2 < 4; i2++) {
                            float xv = fp[i2 * FSTR + f];
                            a[i2][0] += xv * w0;
                            a[i2][1] += xv * w1;
                            a[i2][2] += xv * w2;
                        }
                    }
                    #pragma unroll
                    for (int i2 = 0; i2 < 4; i2++) {
                        hid[(r0 + i2) * HSTR + hc]     = silu_f(a[i2][0] + b1s[hc]);
                        hid[(r0 + i2) * HSTR + hc + 1] = silu_f(a[i2][1] + b1s[hc + 1]);
                        hid[(r0 + i2) * HSTR + hc + 2] = silu_f(a[i2][2] + b1s[hc + 2]);
                    }
                }
            }
            __syncthreads();

            // ---- edge MLP out: we = hidden @ W2, tiles 4 rows x 8 cols ----
            {
                int ntile = (Ej >> 2) * 8;
                for (int t = tid; t < ntile; t += 256) {
                    int rg = t >> 3, cg = t & 7;
                    int r0 = rg << 2, k0 = cg << 3;
                    float a[4][8];
                    #pragma unroll
                    for (int i2 = 0; i2 < 4; i2++)
                        #pragma unroll
                        for (int c = 0; c < 8; c++) a[i2][c] = 0.f;
                    #pragma unroll 8
                    for (int h = 0; h < HP; h++) {
                        float4 wa = *(const float4*)&w2s[h * KD + k0];
                        float4 wb = *(const float4*)&w2s[h * KD + k0 + 4];
                        #pragma unroll
                        for (int i2 = 0; i2 < 4; i2++) {
                            float xv = hid[(r0 + i2) * HSTR + h];
                            a[i2][0] += xv * wa.x; a[i2][1] += xv * wa.y;
                            a[i2][2] += xv * wa.z; a[i2][3] += xv * wa.w;
                            a[i2][4] += xv * wb.x; a[i2][5] += xv * wb.y;
                            a[i2][6] += xv * wb.z; a[i2][7] += xv * wb.w;
                        }
                    }
                    #pragma unroll
                    for (int i2 = 0; i2 < 4; i2++) {
                        *(float4*)&we_s[(r0 + i2) * KD + k0] =
                            make_float4(a[i2][0], a[i2][1], a[i2][2], a[i2][3]);
                        *(float4*)&we_s[(r0 + i2) * KD + k0 + 4] =
                            make_float4(a[i2][4], a[i2][5], a[i2][6], a[i2][7]);
                    }
                }
            }
            __syncthreads();

            // ---- z = segment_sum(we * hx[sender]) using closed-form edge maps ----
            {
                int r  = tid >> 4;
                int k0 = (tid & 15) << 2;
                float4 z = make_float4(0.f, 0.f, 0.f, 0.f);
                if (j == 0) {
                    // same-spin: receiver r, senders = same block, s != r
                    int base = (r < 8) ? 0 : 56;
                    int rr   = r & 7;
                    int sb   = (r < 8) ? 0 : 8;
                    #pragma unroll
                    for (int ss = 0; ss < 8; ss++) {
                        if (ss == rr) continue;
                        int eidx = base + ss * 7 + ((rr < ss) ? rr : rr - 1);
                        float4 w = *(const float4*)&we_s[eidx * KD + k0];
                        float4 h = *(const float4*)&hx[(sb + ss) * KD + k0];
                        z.x += w.x * h.x; z.y += w.y * h.y;
                        z.z += w.z * h.z; z.w += w.w * h.w;
                    }
                } else if (j == 1) {
                    // anti-spin: up receivers get block 2 (64+), down receivers block 1
                    #pragma unroll
                    for (int ss = 0; ss < 8; ss++) {
                        int eidx, sg;
                        if (r < 8) { eidx = 64 + ss * 8 + r;    sg = ss + 8; }
                        else       { eidx = ss * 8 + (r - 8);   sg = ss;     }
                        float4 w = *(const float4*)&we_s[eidx * KD + k0];
                        float4 h = *(const float4*)&hx[NE * KD + sg * KD + k0];
                        z.x += w.x * h.x; z.y += w.y * h.y;
                        z.z += w.z * h.z; z.w += w.w * h.w;
                    }
                } else {
                    // nuc-elec: edge = n*16 + r, weight vector = Y_w[n]
                    #pragma unroll
                    for (int n = 0; n < 4; n++) {
                        int eidx = n * 16 + r;
                        float4 w = *(const float4*)&we_s[eidx * KD + k0];
                        float4 h = *(const float4*)&yw_s[n * KD + k0];
                        z.x += w.x * h.x; z.y += w.y * h.y;
                        z.z += w.z * h.z; z.w += w.w * h.w;
                    }
                }
                *(float4*)&z_s[r * KD + k0] = z;
            }
            __syncthreads();

            // ---- upd += z @ gW[l,j]; thread: rows {rg, rg+8} x 4 cols ----
            {
                int rg = tid >> 5;
                int d0 = (tid & 31) << 2;
                float4 a0 = make_float4(0.f, 0.f, 0.f, 0.f);
                float4 a1 = make_float4(0.f, 0.f, 0.f, 0.f);
                #pragma unroll 8
                for (int k = 0; k < KD; k++) {
                    float4 g = *(const float4*)&wbig[k * DIM + d0];
                    float z0 = z_s[rg * KD + k];
                    float z1 = z_s[(rg + 8) * KD + k];
                    a0.x += z0 * g.x; a0.y += z0 * g.y;
                    a0.z += z0 * g.z; a0.w += z0 * g.w;
                    a1.x += z1 * g.x; a1.y += z1 * g.y;
                    a1.z += z1 * g.z; a1.w += z1 * g.w;
                }
                float4* u0 = (float4*)&upd[rg * DIM + d0];
                float4 v0 = *u0;
                v0.x += a0.x; v0.y += a0.y; v0.z += a0.z; v0.w += a0.w;
                *u0 = v0;
                float4* u1 = (float4*)&upd[(rg + 8) * DIM + d0];
                float4 v1 = *u1;
                v1.x += a1.x; v1.y += a1.y; v1.z += a1.z; v1.w += a1.w;
                *u1 = v1;
            }
            __syncthreads();
        } // j

        // ---- residual update ----
        for (int i = tid; i < NE * DIM; i += 256) elec[i] += upd[i];
        __syncthreads();
    } // l

    // ---- write out ----
    float4* op = (float4*)(out + (size_t)b * NE * DIM);
    const float4* ep = (const float4*)elec;
    for (int i = tid; i < (NE * DIM) / 4; i += 256) op[i] = ep[i];
}

extern "C" void kernel_launch(void* const* d_in, const int* in_sizes, int n_in,
                              void* d_out, int out_size) {
    const float* rs     = (const float*)d_in[0];
    const float* coords = (const float*)d_in[1];
    const float* X_tab  = (const float*)d_in[2];
    const float* Y_w    = (const float*)d_in[3];
    const float* wW1    = (const float*)d_in[4];
    const float* wb1    = (const float*)d_in[5];
    const float* wW2    = (const float*)d_in[6];
    const float* h0t    = (const float*)d_in[7];
    const float* hW     = (const float*)d_in[8];
    const float* gW     = (const float*)d_in[9];
    const int* same_s   = (const int*)d_in[10];
    const int* same_r   = (const int*)d_in[11];
    const int* anti_s   = (const int*)d_in[12];
    const int* anti_r   = (const int*)d_in[13];
    const int* ne_s     = (const int*)d_in[14];
    const int* ne_r     = (const int*)d_in[15];

    int B = in_sizes[0] / (NE * 3);
    size_t smem_bytes = (size_t)SMEM_FLOATS * sizeof(float);
    cudaFuncSetAttribute(schnet_kernel,
                         cudaFuncAttributeMaxDynamicSharedMemorySize,
                         (int)smem_bytes);
    schnet_kernel<<<B, 256, smem_bytes>>>(rs, coords, X_tab, Y_w, wW1, wb1, wW2,
                                          h0t, hW, gW, same_s, same_r,
                                          anti_s, anti_r, ne_s, ne_r,
                                          (float*)d_out);
}

// round 3
// speedup vs baseline: 1.7916x; 1.7916x over previous
#include <cuda_runtime.h>
#include <math.h>

#define NE   16
#define NN   4
#define DIM  128
#define KD   64
#define FD   32
#define HD   45
#define HP   48
#define ES   112
#define EA   128
#define ENE  64
#define ET   304
#define FSTR 33
#define HSTR 49

// ---- shared memory layout (floats) ----
#define OFF_FEATS 0
#define SZ_FEATS  (ET * FSTR)            // 10032
#define OFF_ELEC  (OFF_FEATS + SZ_FEATS)
#define SZ_ELEC   (NE * DIM)             // 2048
#define OFF_HX    (OFF_ELEC + SZ_ELEC)
#define SZ_HX     (2 * NE * KD)          // 2048
#define OFF_UNI   (OFF_HX + SZ_HX)
#define SZ_UNI    (KD * DIM)             // 8192 (holds hid 128*49=6272, or hW/gW 8192)
#define OFF_W1    (OFF_UNI + SZ_UNI)
#define SZ_W1     (FD * HP)              // 1536
#define OFF_B1    (OFF_W1 + SZ_W1)
#define SZ_B1     (HP)                   // 48
#define OFF_W2    (OFF_B1 + SZ_B1)
#define SZ_W2     (HP * KD)              // 3072
#define OFF_Z     (OFF_W2 + SZ_W2)
#define SZ_Z      (NE * KD)              // 1024
#define OFF_YW    (OFF_Z + SZ_Z)
#define SZ_YW     (NN * KD)              // 256
#define SMEM_FLOATS (OFF_YW + SZ_YW)     // 28256 floats = 113,024 B

__device__ __forceinline__ float silu_f(float x) {
    return x / (1.0f + __expf(-x));
}

// stage W1 (padded FDxHP), b1 (HP), W2 (padded HPxKD) for weight-set lj
__device__ __forceinline__ void stage_w12(const float* __restrict__ wW1,
                                          const float* __restrict__ wb1,
                                          const float* __restrict__ wW2,
                                          int lj, float* w1s, float* b1s,
                                          float* w2s, int tid)
{
    const float* W1 = wW1 + (size_t)lj * FD * HD;
    for (int i = tid; i < FD * HP; i += 256) {
        int f = i / HP, h = i - f * HP;
        w1s[i] = (h < HD) ? W1[f * HD + h] : 0.f;
    }
    if (tid < HP) {
        const float* B1 = wb1 + (size_t)lj * HD;
        b1s[tid] = (tid < HD) ? B1[tid] : 0.f;
    }
    const float* W2 = wW2 + (size_t)lj * HD * KD;
    for (int i = tid; i < HP * KD; i += 256) {
        int h = i >> 6;
        w2s[i] = (h < HD) ? W2[i] : 0.f;
    }
}

// fused MLP2 + gather-scatter: per (receiver, k-chunk) thread
template<int CNT>
__device__ __forceinline__ void fused_z(const float* __restrict__ sm,
                                        const float* __restrict__ hid,
                                        const float* __restrict__ w2s,
                                        const int* eoff, const int* hxo,
                                        int k0, float* __restrict__ zp)
{
    float4 wek[CNT];
    #pragma unroll
    for (int e = 0; e < CNT; e++) wek[e] = make_float4(0.f, 0.f, 0.f, 0.f);

    #pragma unroll 6
    for (int h = 0; h < HP; h++) {
        float4 w = *(const float4*)&w2s[h * KD + k0];
        #pragma unroll
        for (int e = 0; e < CNT; e++) {
            float hv = hid[eoff[e] + h];
            wek[e].x += hv * w.x; wek[e].y += hv * w.y;
            wek[e].z += hv * w.z; wek[e].w += hv * w.w;
        }
    }
    float4 acc = make_float4(0.f, 0.f, 0.f, 0.f);
    #pragma unroll
    for (int e = 0; e < CNT; e++) {
        float4 hv = *(const float4*)&sm[hxo[e] + k0];
        acc.x += wek[e].x * hv.x; acc.y += wek[e].y * hv.y;
        acc.z += wek[e].z * hv.z; acc.w += wek[e].w * hv.w;
    }
    *(float4*)zp = acc;
}

__global__ void __launch_bounds__(256, 2)
schnet_kernel(const float* __restrict__ rs,    const float* __restrict__ coords,
              const float* __restrict__ X_tab, const float* __restrict__ Y_w,
              const float* __restrict__ wW1,   const float* __restrict__ wb1,
              const float* __restrict__ wW2,   const float* __restrict__ h0t,
              const float* __restrict__ hW,    const float* __restrict__ gW,
              const int* __restrict__ same_s,  const int* __restrict__ same_r,
              const int* __restrict__ anti_s,  const int* __restrict__ anti_r,
              const int* __restrict__ ne_s,    const int* __restrict__ ne_r,
              float* __restrict__ out)
{
    extern __shared__ float sm[];
    const int b   = blockIdx.x;
    const int tid = threadIdx.x;

    float* feats = sm + OFF_FEATS;
    float* elec  = sm + OFF_ELEC;
    float* hx    = sm + OFF_HX;
    float* uni   = sm + OFF_UNI;   // hid (stride HSTR) OR staged hW/gW
    float* w1s   = sm + OFF_W1;
    float* b1s   = sm + OFF_B1;
    float* w2s   = sm + OFF_W2;
    float* z_s   = sm + OFF_Z;
    float* yw_s  = sm + OFF_YW;

    // ---- init ----
    for (int i = tid; i < NE * DIM; i += 256) elec[i] = X_tab[i & (DIM - 1)];
    for (int i = tid; i < NN * KD;  i += 256) yw_s[i] = Y_w[i];

    // ---- feats: once per sample ----
    const float* rsb = rs + (size_t)b * NE * 3;
    for (int e = tid; e < ET; e += 256) {
        float sx, sy, sz2;
        int r;
        if (e < ES) {
            int s = same_s[e]; r = same_r[e];
            sx = rsb[s*3]; sy = rsb[s*3+1]; sz2 = rsb[s*3+2];
        } else if (e < ES + EA) {
            int q = e - ES; int s = anti_s[q]; r = anti_r[q];
            sx = rsb[s*3]; sy = rsb[s*3+1]; sz2 = rsb[s*3+2];
        } else {
            int q = e - ES - EA; int n = ne_s[q]; r = ne_r[q];
            sx = coords[n*3]; sy = coords[n*3+1]; sz2 = coords[n*3+2];
        }
        float dx = sx - rsb[r*3], dy = sy - rsb[r*3+1], dz = sz2 - rsb[r*3+2];
        float d   = sqrtf(dx*dx + dy*dy + dz*dz);
        float env = d * d * __expf(-d);
        #pragma unroll
        for (int i = 0; i < FD; i++) {
            float q  = (float)i * (1.0f / 31.0f);
            float mu = 10.0f * q * q;
            float sg = (1.0f + 10.0f * q) * (1.0f / 7.0f);
            float t  = (d - mu) / sg;
            feats[e * FSTR + i] = env * __expf(-t * t);
        }
    }
    // prologue: stage weights for lj = 0
    stage_w12(wW1, wb1, wW2, 0, w1s, b1s, w2s, tid);
    __syncthreads();

    for (int l = 0; l < 3; l++) {
        // ---- hx (from elec BEFORE this layer's in-place update) ----
        if (l == 0) {
            for (int i = tid; i < 2 * NE * KD; i += 256)
                hx[i] = h0t[((i >> 10) << 6) + (i & (KD - 1))];
            __syncthreads();
        } else {
            for (int j2 = 0; j2 < 2; j2++) {
                const float* src = hW + (size_t)((l - 1) * 2 + j2) * DIM * KD;
                {
                    const float4* s4 = (const float4*)src;
                    float4* u4 = (float4*)uni;
                    for (int i = tid; i < (DIM * KD) / 4; i += 256) u4[i] = s4[i];
                }
                __syncthreads();
                int s  = tid >> 4;
                int k0 = (tid & 15) << 2;
                float4 acc = make_float4(0.f, 0.f, 0.f, 0.f);
                #pragma unroll 8
                for (int d = 0; d < DIM; d++) {
                    float ev = elec[s * DIM + d];
                    float4 w = *(const float4*)&uni[d * KD + k0];
                    acc.x += ev * w.x; acc.y += ev * w.y;
                    acc.z += ev * w.z; acc.w += ev * w.w;
                }
                __syncthreads();   // uni re-used as hid next; all reads done
                *(float4*)&hx[j2 * NE * KD + s * KD + k0] = acc;
            }
            __syncthreads();
        }

        for (int j = 0; j < 3; j++) {
            const int lj   = l * 3 + j;
            const int Ej   = (j == 0) ? ES : (j == 1) ? EA : ENE;
            const int foff = (j == 0) ? 0  : (j == 1) ? ES : (ES + EA);

            // ---- phase A: edge MLP hidden -> uni (as hid) ----
            {
                float* hid = uni;
                int ntile = (Ej >> 2) * 16;
                for (int t = tid; t < ntile; t += 256) {
                    int rg = t >> 4, cg = t & 15;
                    int r0 = rg << 2, hc = cg * 3;
                    float a[4][3];
                    #pragma unroll
                    for (int i2 = 0; i2 < 4; i2++)
                        { a[i2][0] = 0.f; a[i2][1] = 0.f; a[i2][2] = 0.f; }
                    const float* fp = &feats[(foff + r0) * FSTR];
                    #pragma unroll
                    for (int f = 0; f < FD; f++) {
                        float w0 = w1s[f * HP + hc];
                        float w1 = w1s[f * HP + hc + 1];
                        float w2 = w1s[f * HP + hc + 2];
                        #pragma unroll
                        for (int i2 = 0; i2 < 4; i2++) {
                            float xv = fp[i2 * FSTR + f];
                            a[i2][0] += xv * w0;
                            a[i2][1] += xv * w1;
                            a[i2][2] += xv * w2;
                        }
                    }
                    #pragma unroll
                    for (int i2 = 0; i2 < 4; i2++) {
                        hid[(r0 + i2) * HSTR + hc]     = silu_f(a[i2][0] + b1s[hc]);
                        hid[(r0 + i2) * HSTR + hc + 1] = silu_f(a[i2][1] + b1s[hc + 1]);
                        hid[(r0 + i2) * HSTR + hc + 2] = silu_f(a[i2][2] + b1s[hc + 2]);
                    }
                }
            }
            __syncthreads();

            // ---- phase B: fused MLP2 + segment-sum -> z ----
            {
                int r  = tid >> 4;
                int k0 = (tid & 15) << 2;
                float* zp = &z_s[r * KD + k0];
                if (j == 0) {
                    int base = (r < 8) ? 0 : 56;
                    int rr   = r & 7;
                    int sb   = (r < 8) ? 0 : 8;
                    int eoff[7], hxo[7];
                    int c = 0;
                    #pragma unroll
                    for (int ss = 0; ss < 8; ss++) {
                        if (ss == rr) continue;
                        eoff[c] = (base + ss * 7 + ((rr < ss) ? rr : rr - 1)) * HSTR;
                        hxo[c]  = OFF_HX + (sb + ss) * KD;
                        c++;
                    }
                    fused_z<7>(sm, uni, w2s, eoff, hxo, k0, zp);
                } else if (j == 1) {
                    int eoff[8], hxo[8];
                    #pragma unroll
                    for (int ss = 0; ss < 8; ss++) {
                        int eidx, sg;
                        if (r < 8) { eidx = 64 + ss * 8 + r;  sg = ss + 8; }
                        else       { eidx = ss * 8 + (r - 8); sg = ss;     }
                        eoff[ss] = eidx * HSTR;
                        hxo[ss]  = OFF_HX + NE * KD + sg * KD;
                    }
                    fused_z<8>(sm, uni, w2s, eoff, hxo, k0, zp);
                } else {
                    int eoff[4], hxo[4];
                    #pragma unroll
                    for (int n = 0; n < 4; n++) {
                        eoff[n] = (n * 16 + r) * HSTR;
                        hxo[n]  = OFF_YW + n * KD;
                    }
                    fused_z<4>(sm, uni, w2s, eoff, hxo, k0, zp);
                }
            }
            __syncthreads();

            // ---- phase C: stage gW(lj) -> uni, prefetch next W1/b1/W2 ----
            {
                const float4* g4 = (const float4*)(gW + (size_t)lj * KD * DIM);
                float4* u4 = (float4*)uni;
                for (int i = tid; i < (KD * DIM) / 4; i += 256) u4[i] = g4[i];
                if (lj < 8) stage_w12(wW1, wb1, wW2, lj + 1, w1s, b1s, w2s, tid);
            }
            __syncthreads();

            // ---- phase D: elec += z @ gW (in place) ----
            {
                int rg = tid >> 5;
                int d0 = (tid & 31) << 2;
                float4 a0 = make_float4(0.f, 0.f, 0.f, 0.f);
                float4 a1 = make_float4(0.f, 0.f, 0.f, 0.f);
                #pragma unroll 8
                for (int k = 0; k < KD; k++) {
                    float4 g = *(const float4*)&uni[k * DIM + d0];
                    float z0 = z_s[rg * KD + k];
                    float z1 = z_s[(rg + 8) * KD + k];
                    a0.x += z0 * g.x; a0.y += z0 * g.y;
                    a0.z += z0 * g.z; a0.w += z0 * g.w;
                    a1.x += z1 * g.x; a1.y += z1 * g.y;
                    a1.z += z1 * g.z; a1.w += z1 * g.w;
                }
                float4* u0 = (float4*)&elec[rg * DIM + d0];
                float4 v0 = *u0;
                v0.x += a0.x; v0.y += a0.y; v0.z += a0.z; v0.w += a0.w;
                *u0 = v0;
                float4* u1 = (float4*)&elec[(rg + 8) * DIM + d0];
                float4 v1 = *u1;
                v1.x += a1.x; v1.y += a1.y; v1.z += a1.z; v1.w += a1.w;
                *u1 = v1;
            }
            __syncthreads();
        } // j
    } // l

    // ---- write out ----
    float4* op = (float4*)(out + (size_t)b * NE * DIM);
    const float4* ep = (const float4*)elec;
    for (int i = tid; i < (NE * DIM) / 4; i += 256) op[i] = ep[i];
}

extern "C" void kernel_launch(void* const* d_in, const int* in_sizes, int n_in,
                              void* d_out, int out_size) {
    const float* rs     = (const float*)d_in[0];
    const float* coords = (const float*)d_in[1];
    const float* X_tab  = (const float*)d_in[2];
    const float* Y_w    = (const float*)d_in[3];
    const float* wW1    = (const float*)d_in[4];
    const float* wb1    = (const float*)d_in[5];
    const float* wW2    = (const float*)d_in[6];
    const float* h0t    = (const float*)d_in[7];
    const float* hW     = (const float*)d_in[8];
    const float* gW     = (const float*)d_in[9];
    const int* same_s   = (const int*)d_in[10];
    const int* same_r   = (const int*)d_in[11];
    const int* anti_s   = (const int*)d_in[12];
    const int* anti_r   = (const int*)d_in[13];
    const int* ne_s     = (const int*)d_in[14];
    const int* ne_r     = (const int*)d_in[15];

    int B = in_sizes[0] / (NE * 3);
    size_t smem_bytes = (size_t)SMEM_FLOATS * sizeof(float);
    cudaFuncSetAttribute(schnet_kernel,
                         cudaFuncAttributeMaxDynamicSharedMemorySize,
                         (int)smem_bytes);
    schnet_kernel<<<B, 256, smem_bytes>>>(rs, coords, X_tab, Y_w, wW1, wb1, wW2,
                                          h0t, hW, gW, same_s, same_r,
                                          anti_s, anti_r, ne_s, ne_r,
                                          (float*)d_out);
}

// round 6
// speedup vs baseline: 1.8432x; 1.0288x over previous
#include <cuda_runtime.h>
#include <math.h>

#define NE   16
#define NN   4
#define DIM  128
#define KD   64
#define FD   32
#define HD   45
#define HP   48
#define ES   112
#define EA   128
#define ENE  64
#define ET   304
#define ETP  308     // padded edge count (float4-aligned columns of feats^T)
#define HSTR 52      // hid row stride (float4-aligned, bank-staggered)

// ---- shared memory layout (floats) ----
#define OFF_FEATS 0
#define SZ_FEATS  (FD * ETP)             // 9856  (transposed: [F][ETP])
#define OFF_ELEC  (OFF_FEATS + SZ_FEATS)
#define SZ_ELEC   (NE * DIM)             // 2048
#define OFF_HX    (OFF_ELEC + SZ_ELEC)
#define SZ_HX     (2 * NE * KD)          // 2048
#define OFF_UNI   (OFF_HX + SZ_HX)
#define SZ_UNI    (KD * DIM)             // 8192 (hid 128*52=6656, or hW/gW 8192)
#define OFF_W1    (OFF_UNI + SZ_UNI)
#define SZ_W1     (FD * HP)              // 1536
#define OFF_B1    (OFF_W1 + SZ_W1)
#define SZ_B1     (HP)                   // 48
#define OFF_W2    (OFF_B1 + SZ_B1)
#define SZ_W2     (HP * KD)              // 3072
#define OFF_Z     (OFF_W2 + SZ_W2)
#define SZ_Z      (NE * KD)              // 1024
#define OFF_YW    (OFF_Z + SZ_Z)
#define SZ_YW     (NN * KD)              // 256
#define SMEM_FLOATS (OFF_YW + SZ_YW)     // 28080 floats = 112,320 B

__device__ __forceinline__ float silu_f(float x) {
    return x / (1.0f + __expf(-x));
}

__device__ __forceinline__ void stage_w12(const float* __restrict__ wW1,
                                          const float* __restrict__ wb1,
                                          const float* __restrict__ wW2,
                                          int lj, float* w1s, float* b1s,
                                          float* w2s, int tid)
{
    const float* W1 = wW1 + (size_t)lj * FD * HD;
    for (int i = tid; i < FD * HP; i += 256) {
        int f = i / HP, h = i - f * HP;
        w1s[i] = (h < HD) ? W1[f * HD + h] : 0.f;
    }
    if (tid < HP) {
        const float* B1 = wb1 + (size_t)lj * HD;
        b1s[tid] = (tid < HD) ? B1[tid] : 0.f;
    }
    const float* W2 = wW2 + (size_t)lj * HD * KD;
    for (int i = tid; i < HP * KD; i += 256) {
        int h = i >> 6;
        w2s[i] = (h < HD) ? W2[i] : 0.f;
    }
}

// fused MLP2 + gather-scatter: thread owns (receiver r, 4-wide k chunk k0)
template<int CNT>
__device__ __forceinline__ void fused_z(const float* __restrict__ sm,
                                        const float* __restrict__ hid,
                                        const float* __restrict__ w2s,
                                        const int* eoff, const int* hxo,
                                        int k0, float* __restrict__ zp)
{
    float4 wek[CNT];
    #pragma unroll
    for (int e = 0; e < CNT; e++) wek[e] = make_float4(0.f, 0.f, 0.f, 0.f);

    #pragma unroll 4
    for (int hg = 0; hg < HP / 4; hg++) {
        float4 w0 = *(const float4*)&w2s[(4 * hg + 0) * KD + k0];
        float4 w1 = *(const float4*)&w2s[(4 * hg + 1) * KD + k0];
        float4 w2 = *(const float4*)&w2s[(4 * hg + 2) * KD + k0];
        float4 w3 = *(const float4*)&w2s[(4 * hg + 3) * KD + k0];
        #pragma unroll
        for (int e = 0; e < CNT; e++) {
            float4 hv = *(const float4*)&hid[eoff[e] + 4 * hg];
            wek[e].x += hv.x * w0.x; wek[e].y += hv.x * w0.y;
            wek[e].z += hv.x * w0.z; wek[e].w += hv.x * w0.w;
            wek[e].x += hv.y * w1.x; wek[e].y += hv.y * w1.y;
            wek[e].z += hv.y * w1.z; wek[e].w += hv.y * w1.w;
            wek[e].x += hv.z * w2.x; wek[e].y += hv.z * w2.y;
            wek[e].z += hv.z * w2.z; wek[e].w += hv.z * w2.w;
            wek[e].x += hv.w * w3.x; wek[e].y += hv.w * w3.y;
            wek[e].z += hv.w * w3.z; wek[e].w += hv.w * w3.w;
        }
    }
    float4 acc = make_float4(0.f, 0.f, 0.f, 0.f);
    #pragma unroll
    for (int e = 0; e < CNT; e++) {
        float4 hv = *(const float4*)&sm[hxo[e] + k0];
        acc.x += wek[e].x * hv.x; acc.y += wek[e].y * hv.y;
        acc.z += wek[e].z * hv.z; acc.w += wek[e].w * hv.w;
    }
    *(float4*)zp = acc;
}

__global__ void __launch_bounds__(256, 2)
schnet_kernel(const float* __restrict__ rs,    const float* __restrict__ coords,
              const float* __restrict__ X_tab, const float* __restrict__ Y_w,
              const float* __restrict__ wW1,   const float* __restrict__ wb1,
              const float* __restrict__ wW2,   const float* __restrict__ h0t,
              const float* __restrict__ hW,    const float* __restrict__ gW,
              const int* __restrict__ same_s,  const int* __restrict__ same_r,
              const int* __restrict__ anti_s,  const int* __restrict__ anti_r,
              const int* __restrict__ ne_s,    const int* __restrict__ ne_r,
              float* __restrict__ out)
{
    extern __shared__ float sm[];
    const int b   = blockIdx.x;
    const int tid = threadIdx.x;

    float* featsT = sm + OFF_FEATS;   // [F][ETP]
    float* elec   = sm + OFF_ELEC;
    float* hx     = sm + OFF_HX;
    float* uni    = sm + OFF_UNI;     // hid (stride HSTR) OR staged hW/gW
    float* w1s    = sm + OFF_W1;
    float* b1s    = sm + OFF_B1;
    float* w2s    = sm + OFF_W2;
    float* z_s    = sm + OFF_Z;
    float* yw_s   = sm + OFF_YW;

    // ---- init ----
    for (int i = tid; i < NE * DIM; i += 256) elec[i] = X_tab[i & (DIM - 1)];
    for (int i = tid; i < NN * KD;  i += 256) yw_s[i] = Y_w[i];

    // ---- feats (transposed store): once per sample ----
    const float* rsb = rs + (size_t)b * NE * 3;
    for (int e = tid; e < ET; e += 256) {
        float sx, sy, sz2;
        int r;
        if (e < ES) {
            int s = same_s[e]; r = same_r[e];
            sx = rsb[s*3]; sy = rsb[s*3+1]; sz2 = rsb[s*3+2];
        } else if (e < ES + EA) {
            int q = e - ES; int s = anti_s[q]; r = anti_r[q];
            sx = rsb[s*3]; sy = rsb[s*3+1]; sz2 = rsb[s*3+2];
        } else {
            int q = e - ES - EA; int n = ne_s[q]; r = ne_r[q];
            sx = coords[n*3]; sy = coords[n*3+1]; sz2 = coords[n*3+2];
        }
        float dx = sx - rsb[r*3], dy = sy - rsb[r*3+1], dz = sz2 - rsb[r*3+2];
        float d   = sqrtf(dx*dx + dy*dy + dz*dz);
        float env = d * d * __expf(-d);
        #pragma unroll
        for (int i = 0; i < FD; i++) {
            float q  = (float)i * (1.0f / 31.0f);
            float mu = 10.0f * q * q;
            float sg = (1.0f + 10.0f * q) * (1.0f / 7.0f);
            float t  = (d - mu) / sg;
            featsT[i * ETP + e] = env * __expf(-t * t);
        }
    }
    stage_w12(wW1, wb1, wW2, 0, w1s, b1s, w2s, tid);
    __syncthreads();

    for (int l = 0; l < 3; l++) {
        // ---- hx (from elec BEFORE this layer's in-place update) ----
        if (l == 0) {
            for (int i = tid; i < 2 * NE * KD; i += 256)
                hx[i] = h0t[((i >> 10) << 6) + (i & (KD - 1))];
            __syncthreads();
        } else {
            for (int j2 = 0; j2 < 2; j2++) {
                const float* src = hW + (size_t)((l - 1) * 2 + j2) * DIM * KD;
                {
                    const float4* s4 = (const float4*)src;
                    float4* u4 = (float4*)uni;
                    for (int i = tid; i < (DIM * KD) / 4; i += 256) u4[i] = s4[i];
                }
                __syncthreads();
                int s  = tid >> 4;
                int k0 = (tid & 15) << 2;
                float4 acc = make_float4(0.f, 0.f, 0.f, 0.f);
                #pragma unroll 4
                for (int dg = 0; dg < DIM / 4; dg++) {
                    float4 ev = *(const float4*)&elec[s * DIM + 4 * dg];
                    float4 w0 = *(const float4*)&uni[(4 * dg + 0) * KD + k0];
                    float4 w1 = *(const float4*)&uni[(4 * dg + 1) * KD + k0];
                    float4 w2 = *(const float4*)&uni[(4 * dg + 2) * KD + k0];
                    float4 w3 = *(const float4*)&uni[(4 * dg + 3) * KD + k0];
                    acc.x += ev.x * w0.x; acc.y += ev.x * w0.y;
                    acc.z += ev.x * w0.z; acc.w += ev.x * w0.w;
                    acc.x += ev.y * w1.x; acc.y += ev.y * w1.y;
                    acc.z += ev.y * w1.z; acc.w += ev.y * w1.w;
                    acc.x += ev.z * w2.x; acc.y += ev.z * w2.y;
                    acc.z += ev.z * w2.z; acc.w += ev.z * w2.w;
                    acc.x += ev.w * w3.x; acc.y += ev.w * w3.y;
                    acc.z += ev.w * w3.z; acc.w += ev.w * w3.w;
                }
                __syncthreads();   // uni reads done before it becomes hid
                *(float4*)&hx[j2 * NE * KD + s * KD + k0] = acc;
            }
            __syncthreads();
        }

        for (int j = 0; j < 3; j++) {
            const int lj   = l * 3 + j;
            const int Ej   = (j == 0) ? ES : (j == 1) ? EA : ENE;
            const int foff = (j == 0) ? 0  : (j == 1) ? ES : (ES + EA);

            // ---- phase A: edge MLP hidden -> uni (as hid), 4 edges x 4 cols ----
            {
                float* hid = uni;
                int ntile = (Ej >> 2) * 12;
                for (int t = tid; t < ntile; t += 256) {
                    int rg = t / 12, cg = t - rg * 12;
                    int r0 = rg << 2, hc = cg << 2;
                    float4 a0 = make_float4(0.f, 0.f, 0.f, 0.f);
                    float4 a1 = make_float4(0.f, 0.f, 0.f, 0.f);
                    float4 a2 = make_float4(0.f, 0.f, 0.f, 0.f);
                    float4 a3 = make_float4(0.f, 0.f, 0.f, 0.f);
                    const float* fp = featsT + foff + r0;
                    #pragma unroll
                    for (int f = 0; f < FD; f++) {
                        float4 w = *(const float4*)&w1s[f * HP + hc];
                        float4 x = *(const float4*)&fp[f * ETP];
                        a0.x += x.x * w.x; a0.y += x.x * w.y;
                        a0.z += x.x * w.z; a0.w += x.x * w.w;
                        a1.x += x.y * w.x; a1.y += x.y * w.y;
                        a1.z += x.y * w.z; a1.w += x.y * w.w;
                        a2.x += x.z * w.x; a2.y += x.z * w.y;
                        a2.z += x.z * w.z; a2.w += x.z * w.w;
                        a3.x += x.w * w.x; a3.y += x.w * w.y;
                        a3.z += x.w * w.z; a3.w += x.w * w.w;
                    }
                    float4 bb = *(const float4*)&b1s[hc];
                    float4 o;
                    o.x = silu_f(a0.x + bb.x); o.y = silu_f(a0.y + bb.y);
                    o.z = silu_f(a0.z + bb.z); o.w = silu_f(a0.w + bb.w);
                    *(float4*)&hid[(r0 + 0) * HSTR + hc] = o;
                    o.x = silu_f(a1.x + bb.x); o.y = silu_f(a1.y + bb.y);
                    o.z = silu_f(a1.z + bb.z); o.w = silu_f(a1.w + bb.w);
                    *(float4*)&hid[(r0 + 1) * HSTR + hc] = o;
                    o.x = silu_f(a2.x + bb.x); o.y = silu_f(a2.y + bb.y);
                    o.z = silu_f(a2.z + bb.z); o.w = silu_f(a2.w + bb.w);
                    *(float4*)&hid[(r0 + 2) * HSTR + hc] = o;
                    o.x = silu_f(a3.x + bb.x); o.y = silu_f(a3.y + bb.y);
                    o.z = silu_f(a3.z + bb.z); o.w = silu_f(a3.w + bb.w);
                    *(float4*)&hid[(r0 + 3) * HSTR + hc] = o;
                }
            }
            __syncthreads();

            // ---- phase B: fused MLP2 + segment-sum -> z ----
            {
                int r  = tid >> 4;
                int k0 = (tid & 15) << 2;
                float* zp = &z_s[r * KD + k0];
                if (j == 0) {
                    int base = (r < 8) ? 0 : 56;
                    int rr   = r & 7;
                    int sb   = (r < 8) ? 0 : 8;
                    int eoff[7], hxo[7];
                    int c = 0;
                    #pragma unroll
                    for (int ss = 0; ss < 8; ss++) {
                        if (ss == rr) continue;
                        eoff[c] = (base + ss * 7 + ((rr < ss) ? rr : rr - 1)) * HSTR;
                        hxo[c]  = OFF_HX + (sb + ss) * KD;
                        c++;
                    }
                    fused_z<7>(sm, uni, w2s, eoff, hxo, k0, zp);
                } else if (j == 1) {
                    int eoff[8], hxo[8];
                    #pragma unroll
                    for (int ss = 0; ss < 8; ss++) {
                        int eidx, sg;
                        if (r < 8) { eidx = 64 + ss * 8 + r;  sg = ss + 8; }
                        else       { eidx = ss * 8 + (r - 8); sg = ss;     }
                        eoff[ss] = eidx * HSTR;
                        hxo[ss]  = OFF_HX + NE * KD + sg * KD;
                    }
                    fused_z<8>(sm, uni, w2s, eoff, hxo, k0, zp);
                } else {
                    int eoff[4], hxo[4];
                    #pragma unroll
                    for (int n = 0; n < 4; n++) {
                        eoff[n] = (n * 16 + r) * HSTR;
                        hxo[n]  = OFF_YW + n * KD;
                    }
                    fused_z<4>(sm, uni, w2s, eoff, hxo, k0, zp);
                }
            }
            __syncthreads();

            // ---- phase C: stage gW(lj) -> uni, prefetch next W1/b1/W2 ----
            {
                const float4* g4 = (const float4*)(gW + (size_t)lj * KD * DIM);
                float4* u4 = (float4*)uni;
                for (int i = tid; i < (KD * DIM) / 4; i += 256) u4[i] = g4[i];
                if (lj < 8) stage_w12(wW1, wb1, wW2, lj + 1, w1s, b1s, w2s, tid);
            }
            __syncthreads();

            // ---- phase D: elec += z @ gW (in place) ----
            {
                int rg = tid >> 5;
                int d0 = (tid & 31) << 2;
                float4 a0 = make_float4(0.f, 0.f, 0.f, 0.f);
                float4 a1 = make_float4(0.f, 0.f, 0.f, 0.f);
                #pragma unroll 4
                for (int kg = 0; kg < KD / 4; kg++) {
                    float4 z0 = *(const float4*)&z_s[rg * KD + 4 * kg];
                    float4 z1 = *(const float4*)&z_s[(rg + 8) * KD + 4 * kg];
                    float4 g0 = *(const float4*)&uni[(4 * kg + 0) * DIM + d0];
                    float4 g1 = *(const float4*)&uni[(4 * kg + 1) * DIM + d0];
                    float4 g2 = *(const float4*)&uni[(4 * kg + 2) * DIM + d0];
                    float4 g3 = *(const float4*)&uni[(4 * kg + 3) * DIM + d0];
                    a0.x += z0.x * g0.x; a0.y += z0.x * g0.y;
                    a0.z += z0.x * g0.z; a0.w += z0.x * g0.w;
                    a0.x += z0.y * g1.x; a0.y += z0.y * g1.y;
                    a0.z += z0.y * g1.z; a0.w += z0.y * g1.w;
                    a0.x += z0.z * g2.x; a0.y += z0.z * g2.y;
                    a0.z += z0.z * g2.z; a0.w += z0.z * g2.w;
                    a0.x += z0.w * g3.x; a0.y += z0.w * g3.y;
                    a0.z += z0.w * g3.z; a0.w += z0.w * g3.w;
                    a1.x += z1.x * g0.x; a1.y += z1.x * g0.y;
                    a1.z += z1.x * g0.z; a1.w += z1.x * g0.w;
                    a1.x += z1.y * g1.x; a1.y += z1.y * g1.y;
                    a1.z += z1.y * g1.z; a1.w += z1.y * g1.w;
                    a1.x += z1.z * g2.x; a1.y += z1.z * g2.y;
                    a1.z += z1.z * g2.z; a1.w += z1.z * g2.w;
                    a1.x += z1.w * g3.x; a1.y += z1.w * g3.y;
                    a1.z += z1.w * g3.z; a1.w += z1.w * g3.w;
                }
                float4* u0 = (float4*)&elec[rg * DIM + d0];
                float4 v0 = *u0;
                v0.x += a0.x; v0.y += a0.y; v0.z += a0.z; v0.w += a0.w;
                *u0 = v0;
                float4* u1 = (float4*)&elec[(rg + 8) * DIM + d0];
                float4 v1 = *u1;
                v1.x += a1.x; v1.y += a1.y; v1.z += a1.z; v1.w += a1.w;
                *u1 = v1;
            }
            __syncthreads();
        } // j
    } // l

    // ---- write out ----
    float4* op = (float4*)(out + (size_t)b * NE * DIM);
    const float4* ep = (const float4*)elec;
    for (int i = tid; i < (NE * DIM) / 4; i += 256) op[i] = ep[i];
}

extern "C" void kernel_launch(void* const* d_in, const int* in_sizes, int n_in,
                              void* d_out, int out_size) {
    const float* rs     = (const float*)d_in[0];
    const float* coords = (const float*)d_in[1];
    const float* X_tab  = (const float*)d_in[2];
    const float* Y_w    = (const float*)d_in[3];
    const float* wW1    = (const float*)d_in[4];
    const float* wb1    = (const float*)d_in[5];
    const float* wW2    = (const float*)d_in[6];
    const float* h0t    = (const float*)d_in[7];
    const float* hW     = (const float*)d_in[8];
    const float* gW     = (const float*)d_in[9];
    const int* same_s   = (const int*)d_in[10];
    const int* same_r   = (const int*)d_in[11];
    const int* anti_s   = (const int*)d_in[12];
    const int* anti_r   = (const int*)d_in[13];
    const int* ne_s     = (const int*)d_in[14];
    const int* ne_r     = (const int*)d_in[15];

    int B = in_sizes[0] / (NE * 3);
    size_t smem_bytes = (size_t)SMEM_FLOATS * sizeof(float);
    cudaFuncSetAttribute(schnet_kernel,
                         cudaFuncAttributeMaxDynamicSharedMemorySize,
                         (int)smem_bytes);
    schnet_kernel<<<B, 256, smem_bytes>>>(rs, coords, X_tab, Y_w, wW1, wb1, wW2,
                                          h0t, hW, gW, same_s, same_r,
                                          anti_s, anti_r, ne_s, ne_r,
                                          (float*)d_out);
}